// round 16
// baseline (speedup 1.0000x reference)
#include <cuda_runtime.h>
#include <cuda_fp16.h>
#include <math.h>
#include <stdint.h>

#define MT 16384
#define DD 768
#define NCH 12                       // K chunks of 64
#define A_PLANE (MT * 128)           // bytes per chunk plane (M=16384)
#define W_PLANE (DD * 128)           // bytes per chunk plane (M=768)
#define SZ_X ((size_t)MT * DD * 2)
#define SZ_W ((size_t)DD * DD * 2)
#define PAD_B 32768                  // 256 rows x 128B zero pad before QKV planes
#define SLOT (PAD_B + SZ_X)

// GEMM smem: 2-term stage Ah16|Al16|B16 = 48K (2 CTAs/SM);
//            1-term stage Ah16|B16     = 32K (3 CTAs/SM)
#define GEMM_SMEM2 98304
#define GEMM_SMEM1 65536

// ---- attention (512 threads, k-split p1 / d-split p2) ----
#define TQ 32
#define SSTR 296
#define AT_SH 0
#define AT_SL 18944
#define AT_A  37888
#define P1_STG 45056                 // per stage: KH 36864 | QH 4096 | QL 4096
#define AT_QH 36864
#define AT_QL 40960
#define P2_STG 49152                 // per stage: V rows[js] all 12 chunks
#define ATTN_SMEM 218112             // AT_A + 4*P1_STG

#define INV_SCALE 0.0022552744890219756f

// ---------------------------------------------------------------------------
__device__ __align__(128) uint8_t g_Xh[SZ_X];
__device__ __align__(128) uint8_t g_Xl[SZ_X];
__device__ __align__(128) uint8_t g_Hh[3 * SZ_X];
__device__ __align__(128) uint8_t g_Hl[SZ_X];         // only Q branch
__device__ __align__(128) uint8_t g_W1[3 * SZ_W];
__device__ __align__(128) uint8_t g_W2[3 * SZ_W];
__device__ __align__(128) uint8_t g_QKVh[3 * SLOT];   // zero-init pads
__device__ __align__(128) uint8_t g_QKVl[SLOT];       // only Q lo

__device__ __forceinline__ float gelu_exact(float x) {
    return 0.5f * x * (1.0f + erff(x * 0.70710678118654752f));
}
__device__ __forceinline__ uint32_t s2u(const void* p) {
    uint32_t a;
    asm("{ .reg .u64 t; cvta.to.shared.u64 t, %1; cvt.u32.u64 %0, t; }"
        : "=r"(a) : "l"(p));
    return a;
}
__device__ __forceinline__ size_t toff(int row, int k, size_t plane) {
    const int u = ((k >> 3) & 7) ^ (row & 7);
    return (size_t)(k >> 6) * plane + (size_t)row * 128 + (size_t)(u << 4) + (size_t)(k & 7) * 2;
}

// ---- primitives ----
__device__ __forceinline__ void mma_f16(float* c, const uint32_t* a, const uint32_t* b) {
    asm volatile(
        "mma.sync.aligned.m16n8k16.row.col.f32.f16.f16.f32 "
        "{%0,%1,%2,%3}, {%4,%5,%6,%7}, {%8,%9}, {%0,%1,%2,%3};"
        : "+f"(c[0]), "+f"(c[1]), "+f"(c[2]), "+f"(c[3])
        : "r"(a[0]), "r"(a[1]), "r"(a[2]), "r"(a[3]), "r"(b[0]), "r"(b[1]));
}
__device__ __forceinline__ void ldsm_x4(uint32_t* r, uint32_t addr) {
    asm volatile("ldmatrix.sync.aligned.m8n8.x4.shared.b16 {%0,%1,%2,%3}, [%4];"
                 : "=r"(r[0]), "=r"(r[1]), "=r"(r[2]), "=r"(r[3]) : "r"(addr));
}
__device__ __forceinline__ void ldsm_x4_t(uint32_t* r, uint32_t addr) {
    asm volatile("ldmatrix.sync.aligned.m8n8.x4.trans.shared.b16 {%0,%1,%2,%3}, [%4];"
                 : "=r"(r[0]), "=r"(r[1]), "=r"(r[2]), "=r"(r[3]) : "r"(addr));
}
__device__ __forceinline__ void ldsm_x2(uint32_t* r, uint32_t addr) {
    asm volatile("ldmatrix.sync.aligned.m8n8.x2.shared.b16 {%0,%1}, [%2];"
                 : "=r"(r[0]), "=r"(r[1]) : "r"(addr));
}
#define MB_INIT(addr, cnt) \
    asm volatile("mbarrier.init.shared.b64 [%0], %1;" :: "r"(addr), "r"(cnt) : "memory")
#define MB_EXPECT(addr, tx) \
    asm volatile("mbarrier.arrive.expect_tx.shared.b64 _, [%0], %1;" :: "r"(addr), "r"(tx) : "memory")
#define MB_ARRIVE(addr) \
    asm volatile("mbarrier.arrive.shared.b64 _, [%0];" :: "r"(addr) : "memory")
#define BULK_G2S(dst, src, sz, mb) \
    asm volatile("cp.async.bulk.shared::cluster.global.mbarrier::complete_tx::bytes [%0], [%1], %2, [%3];" \
                 :: "r"(dst), "l"(src), "r"(sz), "r"(mb) : "memory")
#define MB_WAIT(addr, par) do {                                                \
    uint32_t _m = (addr), _p = (par), _d;                                      \
    asm volatile("{\n\t.reg .pred p;\n\t"                                      \
        "mbarrier.try_wait.parity.acquire.cta.shared::cta.b64 p, [%1], %2;\n\t"\
        "selp.b32 %0, 1, 0, p;\n\t}"                                           \
        : "=r"(_d) : "r"(_m), "r"(_p) : "memory");                             \
    if (!_d) {                                                                 \
        asm volatile("{\n\t.reg .pred P1;\n\t"                                 \
            "WL_%=:\n\t"                                                       \
            "mbarrier.try_wait.parity.acquire.cta.shared::cta.b64 P1, [%0], %1, 0x989680;\n\t" \
            "@P1 bra.uni WD_%=;\n\t"                                           \
            "bra.uni WL_%=;\n\t"                                               \
            "WD_%=:\n\t}"                                                      \
            :: "r"(_m), "r"(_p) : "memory");                                   \
    }                                                                          \
} while (0)

__device__ __forceinline__ uint32_t pack_hl_f16(float v, float w, uint32_t& lo) {
    __half h0 = __float2half_rn(v);
    __half h1 = __float2half_rn(w);
    __half l0 = __float2half_rn(v - __half2float(h0));
    __half l1 = __float2half_rn(w - __half2float(h1));
    lo = (uint32_t)__half_as_ushort(l0) | ((uint32_t)__half_as_ushort(l1) << 16);
    return (uint32_t)__half_as_ushort(h0) | ((uint32_t)__half_as_ushort(h1) << 16);
}
__device__ __forceinline__ uint32_t pack_f16(float v, float w) {
    __half h0 = __float2half_rn(v);
    __half h1 = __float2half_rn(w);
    return (uint32_t)__half_as_ushort(h0) | ((uint32_t)__half_as_ushort(h1) << 16);
}

// ---------------------------------------------------------------------------
__global__ void convert_x_kernel(const float* __restrict__ X,
                                 uint8_t* __restrict__ Xh,
                                 uint8_t* __restrict__ Xl) {
    const long gi = (long)(blockIdx.x * blockDim.x + threadIdx.x) * 8;
    const int row = (int)(gi / DD);
    const int k   = (int)(gi % DD);
    const float4 v0 = *(const float4*)(X + gi);
    const float4 v1 = *(const float4*)(X + gi + 4);
    uint32_t h[4], l[4];
    h[0] = pack_hl_f16(v0.x, v0.y, l[0]);
    h[1] = pack_hl_f16(v0.z, v0.w, l[1]);
    h[2] = pack_hl_f16(v1.x, v1.y, l[2]);
    h[3] = pack_hl_f16(v1.z, v1.w, l[3]);
    const size_t o = toff(row, k, A_PLANE);
    *(uint4*)(Xh + o) = make_uint4(h[0], h[1], h[2], h[3]);
    *(uint4*)(Xl + o) = make_uint4(l[0], l[1], l[2], l[3]);
}

__global__ void convert_wt_kernel(const float* __restrict__ qw1,
                                  const float* __restrict__ kw1,
                                  const float* __restrict__ vw1,
                                  const float* __restrict__ qw2,
                                  const float* __restrict__ kw2,
                                  const float* __restrict__ vw2,
                                  uint8_t* __restrict__ W1,
                                  uint8_t* __restrict__ W2) {
    __shared__ float tile[32][33];
    const int z = blockIdx.z;
    const float* W = (z == 0) ? qw1 : (z == 1) ? kw1 : (z == 2) ? vw1
                   : (z == 3) ? qw2 : (z == 4) ? kw2 : vw2;
    uint8_t* dst = (z < 3) ? (W1 + (size_t)z * SZ_W) : (W2 + (size_t)(z - 3) * SZ_W);

    const int bx = blockIdx.x * 32;
    const int by = blockIdx.y * 32;
    const int tx = threadIdx.x, ty = threadIdx.y;
    for (int r = ty; r < 32; r += 8)
        tile[r][tx] = W[(size_t)(by + r) * DD + bx + tx];
    __syncthreads();
    for (int r = ty; r < 32; r += 8) {
        const float v = tile[tx][r];
        const size_t o = toff(bx + r, by + tx, W_PLANE);
        *(__half*)(dst + o) = __float2half_rn(v);
    }
}

// ---------------------------------------------------------------------------
// fp16 GEMM, 128x128 tile, 256 threads.
// TWO=1: A = hi+lo, stage Ah|Al|B 48K, 2 CTAs/SM.
// TWO=0: A = single, stage Ah|B 32K, 3 CTAs/SM (regs capped at 84).
// ---------------------------------------------------------------------------
template<int LAYER, int TWO>
__global__ void __launch_bounds__(256, TWO ? 2 : 3) mma_gemm_kernel(
    const uint8_t* __restrict__ Abh, const uint8_t* __restrict__ Abl,
    const uint8_t* __restrict__ Bb,
    const float* __restrict__ bias0, const float* __restrict__ bias1,
    const float* __restrict__ bias2,
    uint8_t* __restrict__ Ch, uint8_t* __restrict__ Cl, int zbase)
{
    constexpr uint32_t STG_B_T = TWO ? 32768u : 16384u;
    constexpr uint32_t STAGE_T = TWO ? 49152u : 32768u;

    extern __shared__ char sm[];
    __shared__ uint64_t s_mbar[4];
    const uint32_t smb = s2u(sm);
    const uint32_t mb0 = s2u(&s_mbar[0]);

    const int t    = threadIdx.x;
    const int warp = t >> 5;
    const int lane = t & 31;
    const int wm   = warp & 3;
    const int wn   = warp >> 2;
    const int n0   = blockIdx.x * 128;
    const int m0   = blockIdx.y * 128;
    const int z    = blockIdx.z + zbase;

    const uint8_t* Ah = Abh + (LAYER == 2 ? (size_t)z * SZ_X : 0);
    const uint8_t* Al = Abl;   // only valid when TWO (z==0)
    const uint8_t* Bp = Bb + (size_t)z * SZ_W;
    const float* bias = (z == 0) ? bias0 : (z == 1) ? bias1 : bias2;

    if (t == 0) {
        MB_INIT(mb0, 1);  MB_INIT(mb0 + 8, 1);
        MB_INIT(mb0 + 16, 8);  MB_INIT(mb0 + 24, 8);
    }
    __syncthreads();

    auto load_chunk = [&](int c, int s) {
        const uint32_t sb = smb + s * STAGE_T;
        const uint32_t mb = mb0 + s * 8;
        MB_EXPECT(mb, STAGE_T);
        BULK_G2S(sb,          Ah + (size_t)c * A_PLANE + (size_t)m0 * 128, 16384, mb);
        if (TWO)
            BULK_G2S(sb + 16384, Al + (size_t)c * A_PLANE + (size_t)m0 * 128, 16384, mb);
        BULK_G2S(sb + STG_B_T, Bp + (size_t)c * W_PLANE + (size_t)n0 * 128, 16384, mb);
    };

    const int l15   = lane & 15;
    const int uA    = lane >> 4;
    const int q3    = lane >> 3;
    const int brl   = lane & 7;
    const int brow  = (q3 < 2) ? brl : (8 + brl);
    const int uB    = q3 & 1;

    float acc[2][8][4];
    #pragma unroll
    for (int i = 0; i < 2; i++)
        #pragma unroll
        for (int j = 0; j < 8; j++)
            #pragma unroll
            for (int r = 0; r < 4; r++) acc[i][j][r] = 0.f;

    if (t == 0) load_chunk(0, 0);
    int pf[2] = {0, 0}, pe[2] = {0, 0};

    for (int c = 0; c < NCH; ++c) {
        const int s = c & 1;
        if (c + 1 < NCH && t == 0) {
            if (c >= 1) { MB_WAIT(mb0 + 16 + (s ^ 1) * 8, pe[s ^ 1]); pe[s ^ 1] ^= 1; }
            load_chunk(c + 1, s ^ 1);
        }
        MB_WAIT(mb0 + s * 8, pf[s]);
        pf[s] ^= 1;

        const uint32_t sb = smb + s * STAGE_T;
        #pragma unroll
        for (int k16 = 0; k16 < 64; k16 += 16) {
            uint32_t ah[2][4], al[2][4];
            #pragma unroll
            for (int mt = 0; mt < 2; mt++) {
                const int row = wm * 32 + mt * 16 + l15;
                const int u   = ((k16 >> 3) + uA) ^ (row & 7);
                const uint32_t ao = (uint32_t)(row * 128 + (u << 4));
                ldsm_x4(ah[mt], sb + ao);
                if (TWO) ldsm_x4(al[mt], sb + 16384 + ao);
            }
            #pragma unroll
            for (int p = 0; p < 4; p++) {
                const int row = wn * 64 + p * 16 + brow;
                const int u   = ((k16 >> 3) + uB) ^ (row & 7);
                const uint32_t bo = (uint32_t)(row * 128 + (u << 4));
                uint32_t rh[4];
                ldsm_x4(rh, sb + STG_B_T + bo);
                #pragma unroll
                for (int h = 0; h < 2; h++) {
                    const int nt = 2 * p + h;
                    #pragma unroll
                    for (int mt = 0; mt < 2; mt++) {
                        mma_f16(acc[mt][nt], ah[mt], rh + 2 * h);
                        if (TWO) mma_f16(acc[mt][nt], al[mt], rh + 2 * h);
                    }
                }
            }
        }
        if (lane == 0) MB_ARRIVE(mb0 + 16 + s * 8);
    }

    const int gid = lane >> 2;
    const int qid = lane & 3;
    #pragma unroll
    for (int mt = 0; mt < 2; mt++) {
        #pragma unroll
        for (int nt = 0; nt < 8; nt++) {
            const int col = n0 + wn * 64 + nt * 8 + qid * 2;
            const float b0 = bias[col], b1 = bias[col + 1];
            #pragma unroll
            for (int half = 0; half < 2; half++) {
                const int row = m0 + wm * 32 + mt * 16 + gid + half * 8;
                float v0 = acc[mt][nt][half * 2]     + b0;
                float v1 = acc[mt][nt][half * 2 + 1] + b1;
                if (LAYER == 1) { v0 = gelu_exact(v0); v1 = gelu_exact(v1); }
                const size_t o = (LAYER == 1)
                    ? (size_t)z * SZ_X + toff(row, col, A_PLANE)
                    : (size_t)z * SLOT + PAD_B + toff(row, col, A_PLANE);
                if (TWO) {
                    uint32_t lo;
                    const uint32_t hi = pack_hl_f16(v0, v1, lo);
                    *(uint32_t*)(Ch + o) = hi;
                    *(uint32_t*)(Cl + o) = lo;
                } else {
                    *(uint32_t*)(Ch + o) = pack_f16(v0, v1);
                }
            }
        }
    }
}

// ---------------------------------------------------------------------------
// Banded attention + LN, 512 threads (verbatim round 13/14 — proven).
// ---------------------------------------------------------------------------
__global__ void __launch_bounds__(512, 1) attn_kernel(
    const uint8_t* __restrict__ Qh, const uint8_t* __restrict__ Ql,
    const uint8_t* __restrict__ Kh, const uint8_t* __restrict__ Vh,
    const float* __restrict__ lnw, const float* __restrict__ lnb,
    float* __restrict__ out)
{
    extern __shared__ char smc[];
    __shared__ uint64_t s_mb[12];
    __shared__ float2 s_part[32][8];
    const uint32_t smb = s2u(smc);
    const uint32_t smA = smb + AT_A;
    const uint32_t mb = s2u(&s_mb[0]);

    const int t    = threadIdx.x;
    const int warp = t >> 5;
    const int lane = t & 31;
    const int g    = warp >> 3;
    const int wg   = warp & 7;
    const int wm   = wg >> 2;
    const int wn   = wg & 3;
    const int gid  = lane >> 2;
    const int qid  = lane & 3;
    const int tg   = t & 255;

    const int bx = blockIdx.x;
    const int b  = bx >> 7;
    const int i0 = (bx & 127) * TQ;
    const long base = (long)b * 4096;
    const long gq   = base + i0;
    const long gk   = base + i0 - 256;
    const int jb = i0 - 256;

    const int l15  = lane & 15;
    const int uA   = lane >> 4;
    const int q3   = lane >> 3;
    const int brl  = lane & 7;
    const int brow = (q3 < 2) ? brl : (8 + brl);
    const int uB   = q3 & 1;

    if (t == 0) {
        #pragma unroll
        for (int i = 0; i < 4; i++) { MB_INIT(mb + i * 8, 1); MB_INIT(mb + 32 + i * 8, 8); }
        MB_INIT(mb + 64, 1); MB_INIT(mb + 72, 1);
        MB_INIT(mb + 80, 16); MB_INIT(mb + 88, 16);
    }
    __syncthreads();

    // phase 1
    auto p1_load = [&](int cl, int s) {
        const int cg = g * 6 + cl;
        const uint32_t sb = smA + (g * 2 + s) * P1_STG;
        const uint32_t m1 = mb + (g * 2 + s) * 8;
        MB_EXPECT(m1, 45056);
        BULK_G2S(sb,         Kh + ((long)cg * A_PLANE + gk * 128), 36864, m1);
        BULK_G2S(sb + AT_QH, Qh + ((long)cg * A_PLANE + gq * 128), 4096, m1);
        BULK_G2S(sb + AT_QL, Ql + ((long)cg * A_PLANE + gq * 128), 4096, m1);
    };

    float acc[9][4];
    #pragma unroll
    for (int n = 0; n < 9; n++)
        #pragma unroll
        for (int r = 0; r < 4; r++) acc[n][r] = 0.f;

    if (tg == 0) { p1_load(0, 0); p1_load(1, 1); }
    int pf1[2] = {0, 0}, pe1[2] = {0, 0};

    for (int cl = 0; cl < 6; ++cl) {
        const int s = cl & 1;
        MB_WAIT(mb + (g * 2 + s) * 8, pf1[s]);
        pf1[s] ^= 1;

        const uint32_t sb = smA + (g * 2 + s) * P1_STG;
        #pragma unroll
        for (int k16 = 0; k16 < 64; k16 += 16) {
            uint32_t ah[4], al[4];
            {
                const int row = wm * 16 + l15;
                const int u   = ((k16 >> 3) + uA) ^ (row & 7);
                const uint32_t ao = (uint32_t)(row * 128 + (u << 4));
                ldsm_x4(ah, sb + AT_QH + ao);
                ldsm_x4(al, sb + AT_QL + ao);
            }
            uint32_t bh[9][2];
            #pragma unroll
            for (int p = 0; p < 4; p++) {
                const int row = wn * 72 + p * 16 + brow;
                const int u   = ((k16 >> 3) + uB) ^ (row & 7);
                const uint32_t bo = (uint32_t)(row * 128 + (u << 4));
                uint32_t r4[4];
                ldsm_x4(r4, sb + bo);
                bh[2*p][0] = r4[0]; bh[2*p][1] = r4[1];
                bh[2*p+1][0] = r4[2]; bh[2*p+1][1] = r4[3];
            }
            {
                const int row = wn * 72 + 64 + brl;
                const int u   = ((k16 >> 3) + ((lane >> 3) & 1)) ^ (row & 7);
                const uint32_t bo = (uint32_t)(row * 128 + (u << 4));
                ldsm_x2(bh[8], sb + bo);
            }
            #pragma unroll
            for (int nt = 0; nt < 9; nt++) {
                mma_f16(acc[nt], ah, bh[nt]);
                mma_f16(acc[nt], al, bh[nt]);
            }
        }
        if (lane == 0) MB_ARRIVE(mb + 32 + (g * 2 + s) * 8);
        if (tg == 0 && cl + 2 < 6) {
            MB_WAIT(mb + 32 + (g * 2 + s) * 8, pe1[s]); pe1[s] ^= 1;
            p1_load(cl + 2, s);
        }
    }

    __syncthreads();
    float* scr = (float*)(smc + AT_A);
    if (g == 1) {
        #pragma unroll
        for (int nt = 0; nt < 9; nt++)
            #pragma unroll
            for (int r = 0; r < 4; r++)
                scr[tg * 36 + nt * 4 + r] = acc[nt][r];
    }
    __syncthreads();
    if (g == 0) {
        #pragma unroll
        for (int nt = 0; nt < 9; nt++) {
            const int jw0 = wn * 72 + nt * 8 + qid * 2;
            #pragma unroll
            for (int half = 0; half < 2; half++) {
                const int ti = wm * 16 + gid + half * 8;
                float v0 = acc[nt][half * 2]     + scr[tg * 36 + nt * 4 + half * 2];
                float v1 = acc[nt][half * 2 + 1] + scr[tg * 36 + nt * 4 + half * 2 + 1];
                const bool ok0 = (jb + jw0     >= 0) && (jw0     > ti) && (jw0     <= ti + 256);
                const bool ok1 = (jb + jw0 + 1 >= 0) && (jw0 + 1 > ti) && (jw0 + 1 <= ti + 256);
                v0 = ok0 ? v0 * INV_SCALE : 0.f;
                v1 = ok1 ? v1 * INV_SCALE : 0.f;
                uint32_t lo;
                const uint32_t hi = pack_hl_f16(v0, v1, lo);
                const uint32_t so = (uint32_t)(ti * SSTR + jw0) * 2;
                *(uint32_t*)(smc + AT_SH + so) = hi;
                *(uint32_t*)(smc + AT_SL + so) = lo;
            }
        }
    }
    __syncthreads();

    // phase 2
    auto p2_load = [&](int js, int s) {
        const long r0 = gk + (long)js * 32;
        const uint32_t sb = smA + s * P2_STG;
        const uint32_t m2 = mb + 64 + s * 8;
        MB_EXPECT(m2, 49152);
        #pragma unroll
        for (int cv = 0; cv < 12; cv++)
            BULK_G2S(sb + cv * 4096, Vh + ((long)cv * A_PLANE + r0 * 128), 4096, m2);
    };

    float acc2[12][4];
    #pragma unroll
    for (int n = 0; n < 12; n++)
        #pragma unroll
        for (int r = 0; r < 4; r++) acc2[n][r] = 0.f;

    if (t == 0) { p2_load(0, 0); p2_load(1, 1); }
    int pf2[2] = {0, 0}, pe2[2] = {0, 0};

    for (int js = 0; js < 9; ++js) {
        const int s = js & 1;
        MB_WAIT(mb + 64 + s * 8, pf2[s]);
        pf2[s] ^= 1;

        const uint32_t sb = smA + s * P2_STG;
        #pragma unroll
        for (int k16 = 0; k16 < 32; k16 += 16) {
            uint32_t ah[4], al[4];
            const uint32_t ao = (uint32_t)((wm * 16 + l15) * SSTR + js * 32 + k16 + uA * 8) * 2;
            ldsm_x4(ah, smb + AT_SH + ao);
            ldsm_x4(al, smb + AT_SL + ao);

            const int row = k16 + l15;
            #pragma unroll
            for (int cp = 0; cp < 6; cp++) {
                const int cg = g * 384 + wn * 96 + cp * 16;
                const int cv = cg >> 6;
                const int u0 = (cg & 63) >> 3;
                const int u  = (u0 + uA) ^ (row & 7);
                const uint32_t bo = (uint32_t)(cv * 4096 + row * 128 + (u << 4));
                uint32_t r4[4];
                ldsm_x4_t(r4, sb + bo);
                mma_f16(acc2[2*cp],   ah, r4);
                mma_f16(acc2[2*cp],   al, r4);
                mma_f16(acc2[2*cp+1], ah, r4 + 2);
                mma_f16(acc2[2*cp+1], al, r4 + 2);
            }
        }
        if (lane == 0) MB_ARRIVE(mb + 80 + s * 8);
        if (t == 0 && js + 2 < 9) {
            MB_WAIT(mb + 80 + s * 8, pe2[s]); pe2[s] ^= 1;
            p2_load(js + 2, s);
        }
    }

    // LN from registers
    {
        float sum[2] = {0.f, 0.f}, ssq[2] = {0.f, 0.f};
        #pragma unroll
        for (int nt = 0; nt < 12; nt++) {
            #pragma unroll
            for (int half = 0; half < 2; half++) {
                const float a = acc2[nt][half * 2];
                const float c = acc2[nt][half * 2 + 1];
                sum[half] += a + c;
                ssq[half] += a * a + c * c;
            }
        }
        #pragma unroll
        for (int o = 1; o <= 2; o <<= 1) {
            #pragma unroll
            for (int half = 0; half < 2; half++) {
                sum[half] += __shfl_xor_sync(0xffffffffu, sum[half], o);
                ssq[half] += __shfl_xor_sync(0xffffffffu, ssq[half], o);
            }
        }
        if (qid == 0) {
            #pragma unroll
            for (int half = 0; half < 2; half++) {
                const int row = wm * 16 + gid + half * 8;
                s_part[row][g * 4 + wn] = make_float2(sum[half], ssq[half]);
            }
        }
        __syncthreads();

        #pragma unroll
        for (int half = 0; half < 2; half++) {
            const int row = wm * 16 + gid + half * 8;
            float S = 0.f, SS = 0.f;
            #pragma unroll
            for (int i = 0; i < 8; i++) {
                const float2 p = s_part[row][i];
                S += p.x; SS += p.y;
            }
            const float mu   = S * (1.f / 768.f);
            const float var  = SS * (1.f / 768.f) - mu * mu;
            const float rstd = rsqrtf(var + 1e-5f);
            float* orow = out + (gq + row) * DD;
            #pragma unroll
            for (int nt = 0; nt < 12; nt++) {
                const int col = g * 384 + wn * 96 + (nt >> 1) * 16 + (nt & 1) * 8 + qid * 2;
                const float v0 = acc2[nt][half * 2];
                const float v1 = acc2[nt][half * 2 + 1];
                const float2 w2 = *(const float2*)(lnw + col);
                const float2 b2 = *(const float2*)(lnb + col);
                float2 r;
                r.x = (v0 - mu) * rstd * w2.x + b2.x;
                r.y = (v1 - mu) * rstd * w2.y + b2.y;
                *(float2*)(orow + col) = r;
            }
        }
    }
}

// ---------------------------------------------------------------------------
extern "C" void kernel_launch(void* const* d_in, const int* in_sizes, int n_in,
                              void* d_out, int out_size)
{
    const float* x   = (const float*)d_in[0];
    const float* qw1 = (const float*)d_in[1];
    const float* qb1 = (const float*)d_in[2];
    const float* qw2 = (const float*)d_in[3];
    const float* qb2 = (const float*)d_in[4];
    const float* kw1 = (const float*)d_in[5];
    const float* kb1 = (const float*)d_in[6];
    const float* kw2 = (const float*)d_in[7];
    const float* kb2 = (const float*)d_in[8];
    const float* vw1 = (const float*)d_in[9];
    const float* vb1 = (const float*)d_in[10];
    const float* vw2 = (const float*)d_in[11];
    const float* vb2 = (const float*)d_in[12];
    const float* lnw = (const float*)d_in[13];
    const float* lnb = (const float*)d_in[14];
    float* out = (float*)d_out;

    uint8_t *Xh, *Xl, *Hh, *Hl, *W1, *W2, *QKVh, *QKVl;
    cudaGetSymbolAddress((void**)&Xh, g_Xh);
    cudaGetSymbolAddress((void**)&Xl, g_Xl);
    cudaGetSymbolAddress((void**)&Hh, g_Hh);
    cudaGetSymbolAddress((void**)&Hl, g_Hl);
    cudaGetSymbolAddress((void**)&W1, g_W1);
    cudaGetSymbolAddress((void**)&W2, g_W2);
    cudaGetSymbolAddress((void**)&QKVh, g_QKVh);
    cudaGetSymbolAddress((void**)&QKVl, g_QKVl);

    cudaFuncSetAttribute(mma_gemm_kernel<1, 1>,
                         cudaFuncAttributeMaxDynamicSharedMemorySize, GEMM_SMEM2);
    cudaFuncSetAttribute(mma_gemm_kernel<1, 0>,
                         cudaFuncAttributeMaxDynamicSharedMemorySize, GEMM_SMEM1);
    cudaFuncSetAttribute(mma_gemm_kernel<2, 1>,
                         cudaFuncAttributeMaxDynamicSharedMemorySize, GEMM_SMEM2);
    cudaFuncSetAttribute(mma_gemm_kernel<2, 0>,
                         cudaFuncAttributeMaxDynamicSharedMemorySize, GEMM_SMEM1);
    cudaFuncSetAttribute(attn_kernel,
                         cudaFuncAttributeMaxDynamicSharedMemorySize, ATTN_SMEM);

    convert_x_kernel<<<(MT * DD) / (256 * 8), 256>>>(x, Xh, Xl);

    const dim3 gw(24, 24, 6);
    const dim3 bw(32, 8);
    convert_wt_kernel<<<gw, bw>>>(qw1, kw1, vw1, qw2, kw2, vw2, W1, W2);

    const dim3 g1(DD / 128, MT / 128, 1);   // Q branch (2-term)
    const dim3 g2(DD / 128, MT / 128, 2);   // K,V branches (1-term)

    mma_gemm_kernel<1, 1><<<g1, 256, GEMM_SMEM2>>>(Xh, Xl, W1,
                                                   qb1, kb1, vb1, Hh, Hl, 0);
    mma_gemm_kernel<1, 0><<<g2, 256, GEMM_SMEM1>>>(Xh, nullptr, W1,
                                                   qb1, kb1, vb1, Hh, nullptr, 1);
    mma_gemm_kernel<2, 1><<<g1, 256, GEMM_SMEM2>>>(Hh, Hl, W2,
                                                   qb2, kb2, vb2, QKVh, QKVl, 0);
    mma_gemm_kernel<2, 0><<<g2, 256, GEMM_SMEM1>>>(Hh, nullptr, W2,
                                                   qb2, kb2, vb2, QKVh, nullptr, 1);

    attn_kernel<<<MT / TQ, 512, ATTN_SMEM>>>(
        QKVh + PAD_B,               QKVl + PAD_B,
        QKVh + SLOT + PAD_B,
        QKVh + 2ull * SLOT + PAD_B,
        lnw, lnb, out);
}

// round 17
// speedup vs baseline: 1.6652x; 1.6652x over previous
#include <cuda_runtime.h>
#include <cuda_fp16.h>
#include <math.h>
#include <stdint.h>

#define MT 16384
#define DD 768
#define NCH 12                       // K chunks of 64
#define A_PLANE (MT * 128)           // bytes per chunk plane (M=16384)
#define W_PLANE (DD * 128)           // bytes per chunk plane (M=768)
#define SZ_X ((size_t)MT * DD * 2)
#define SZ_W ((size_t)DD * DD * 2)
#define PAD_B 32768                  // 256 rows x 128B zero pad before QKV planes
#define SLOT (PAD_B + SZ_X)

// GEMM smem stage: Ah 16K | B 16K (1-term), 2 stages, 2 CTAs/SM
#define STG_B  16384
#define STAGE  32768
#define GEMM_SMEM (2 * STAGE)

// ---- attention (512 threads, k-split p1 / d-split p2, all 1-term) ----
#define TQ 32
#define SSTR 296
#define AT_SH 0                      // S hi only: 32*296*2 = 18944
#define AT_A  18944
#define P1_STG 40960                 // per stage: KH 36864 | QH 4096
#define AT_QH 36864
#define P2_STG 49152                 // per stage: V rows[js] all 12 chunks
#define ATTN_SMEM 182784             // AT_A + 4*P1_STG

#define INV_SCALE 0.0022552744890219756f

// ---------------------------------------------------------------------------
__device__ __align__(128) uint8_t g_Xh[SZ_X];
__device__ __align__(128) uint8_t g_Hh[3 * SZ_X];
__device__ __align__(128) uint8_t g_W1[3 * SZ_W];
__device__ __align__(128) uint8_t g_W2[3 * SZ_W];
__device__ __align__(128) uint8_t g_QKVh[3 * SLOT];   // zero-init pads

__device__ __forceinline__ float gelu_exact(float x) {
    return 0.5f * x * (1.0f + erff(x * 0.70710678118654752f));
}
__device__ __forceinline__ uint32_t s2u(const void* p) {
    uint32_t a;
    asm("{ .reg .u64 t; cvta.to.shared.u64 t, %1; cvt.u32.u64 %0, t; }"
        : "=r"(a) : "l"(p));
    return a;
}
__device__ __forceinline__ size_t toff(int row, int k, size_t plane) {
    const int u = ((k >> 3) & 7) ^ (row & 7);
    return (size_t)(k >> 6) * plane + (size_t)row * 128 + (size_t)(u << 4) + (size_t)(k & 7) * 2;
}

// ---- primitives ----
__device__ __forceinline__ void mma_f16(float* c, const uint32_t* a, const uint32_t* b) {
    asm volatile(
        "mma.sync.aligned.m16n8k16.row.col.f32.f16.f16.f32 "
        "{%0,%1,%2,%3}, {%4,%5,%6,%7}, {%8,%9}, {%0,%1,%2,%3};"
        : "+f"(c[0]), "+f"(c[1]), "+f"(c[2]), "+f"(c[3])
        : "r"(a[0]), "r"(a[1]), "r"(a[2]), "r"(a[3]), "r"(b[0]), "r"(b[1]));
}
__device__ __forceinline__ void ldsm_x4(uint32_t* r, uint32_t addr) {
    asm volatile("ldmatrix.sync.aligned.m8n8.x4.shared.b16 {%0,%1,%2,%3}, [%4];"
                 : "=r"(r[0]), "=r"(r[1]), "=r"(r[2]), "=r"(r[3]) : "r"(addr));
}
__device__ __forceinline__ void ldsm_x4_t(uint32_t* r, uint32_t addr) {
    asm volatile("ldmatrix.sync.aligned.m8n8.x4.trans.shared.b16 {%0,%1,%2,%3}, [%4];"
                 : "=r"(r[0]), "=r"(r[1]), "=r"(r[2]), "=r"(r[3]) : "r"(addr));
}
__device__ __forceinline__ void ldsm_x2(uint32_t* r, uint32_t addr) {
    asm volatile("ldmatrix.sync.aligned.m8n8.x2.shared.b16 {%0,%1}, [%2];"
                 : "=r"(r[0]), "=r"(r[1]) : "r"(addr));
}
#define MB_INIT(addr, cnt) \
    asm volatile("mbarrier.init.shared.b64 [%0], %1;" :: "r"(addr), "r"(cnt) : "memory")
#define MB_EXPECT(addr, tx) \
    asm volatile("mbarrier.arrive.expect_tx.shared.b64 _, [%0], %1;" :: "r"(addr), "r"(tx) : "memory")
#define MB_ARRIVE(addr) \
    asm volatile("mbarrier.arrive.shared.b64 _, [%0];" :: "r"(addr) : "memory")
#define BULK_G2S(dst, src, sz, mb) \
    asm volatile("cp.async.bulk.shared::cluster.global.mbarrier::complete_tx::bytes [%0], [%1], %2, [%3];" \
                 :: "r"(dst), "l"(src), "r"(sz), "r"(mb) : "memory")
#define MB_WAIT(addr, par) do {                                                \
    uint32_t _m = (addr), _p = (par), _d;                                      \
    asm volatile("{\n\t.reg .pred p;\n\t"                                      \
        "mbarrier.try_wait.parity.acquire.cta.shared::cta.b64 p, [%1], %2;\n\t"\
        "selp.b32 %0, 1, 0, p;\n\t}"                                           \
        : "=r"(_d) : "r"(_m), "r"(_p) : "memory");                             \
    if (!_d) {                                                                 \
        asm volatile("{\n\t.reg .pred P1;\n\t"                                 \
            "WL_%=:\n\t"                                                       \
            "mbarrier.try_wait.parity.acquire.cta.shared::cta.b64 P1, [%0], %1, 0x989680;\n\t" \
            "@P1 bra.uni WD_%=;\n\t"                                           \
            "bra.uni WL_%=;\n\t"                                               \
            "WD_%=:\n\t}"                                                      \
            :: "r"(_m), "r"(_p) : "memory");                                   \
    }                                                                          \
} while (0)

__device__ __forceinline__ uint32_t pack_f16(float v, float w) {
    __half h0 = __float2half_rn(v);
    __half h1 = __float2half_rn(w);
    return (uint32_t)__half_as_ushort(h0) | ((uint32_t)__half_as_ushort(h1) << 16);
}

// ---------------------------------------------------------------------------
__global__ void convert_x_kernel(const float* __restrict__ X,
                                 uint8_t* __restrict__ Xh) {
    const long gi = (long)(blockIdx.x * blockDim.x + threadIdx.x) * 8;
    const int row = (int)(gi / DD);
    const int k   = (int)(gi % DD);
    const float4 v0 = *(const float4*)(X + gi);
    const float4 v1 = *(const float4*)(X + gi + 4);
    uint32_t h[4];
    h[0] = pack_f16(v0.x, v0.y);
    h[1] = pack_f16(v0.z, v0.w);
    h[2] = pack_f16(v1.x, v1.y);
    h[3] = pack_f16(v1.z, v1.w);
    const size_t o = toff(row, k, A_PLANE);
    *(uint4*)(Xh + o) = make_uint4(h[0], h[1], h[2], h[3]);
}

__global__ void convert_wt_kernel(const float* __restrict__ qw1,
                                  const float* __restrict__ kw1,
                                  const float* __restrict__ vw1,
                                  const float* __restrict__ qw2,
                                  const float* __restrict__ kw2,
                                  const float* __restrict__ vw2,
                                  uint8_t* __restrict__ W1,
                                  uint8_t* __restrict__ W2) {
    __shared__ float tile[32][33];
    const int z = blockIdx.z;
    const float* W = (z == 0) ? qw1 : (z == 1) ? kw1 : (z == 2) ? vw1
                   : (z == 3) ? qw2 : (z == 4) ? kw2 : vw2;
    uint8_t* dst = (z < 3) ? (W1 + (size_t)z * SZ_W) : (W2 + (size_t)(z - 3) * SZ_W);

    const int bx = blockIdx.x * 32;
    const int by = blockIdx.y * 32;
    const int tx = threadIdx.x, ty = threadIdx.y;
    for (int r = ty; r < 32; r += 8)
        tile[r][tx] = W[(size_t)(by + r) * DD + bx + tx];
    __syncthreads();
    for (int r = ty; r < 32; r += 8) {
        const float v = tile[tx][r];
        const size_t o = toff(bx + r, by + tx, W_PLANE);
        *(__half*)(dst + o) = __float2half_rn(v);
    }
}

// ---------------------------------------------------------------------------
// fp16 1-term GEMM, 128x128 tile, 256 threads, 2 CTAs/SM, grid z = branch.
// LAYER 1 -> tiled H (+gelu). LAYER 2 -> tiled QKV.
// ---------------------------------------------------------------------------
template<int LAYER>
__global__ void __launch_bounds__(256, 2) mma_gemm_kernel(
    const uint8_t* __restrict__ Ab, const uint8_t* __restrict__ Bb,
    const float* __restrict__ bias0, const float* __restrict__ bias1,
    const float* __restrict__ bias2,
    uint8_t* __restrict__ C)
{
    extern __shared__ char sm[];
    __shared__ uint64_t s_mbar[4];
    const uint32_t smb = s2u(sm);
    const uint32_t mb0 = s2u(&s_mbar[0]);

    const int t    = threadIdx.x;
    const int warp = t >> 5;
    const int lane = t & 31;
    const int wm   = warp & 3;
    const int wn   = warp >> 2;
    const int n0   = blockIdx.x * 128;
    const int m0   = blockIdx.y * 128;
    const int z    = blockIdx.z;

    const uint8_t* Ah = Ab + (LAYER == 2 ? (size_t)z * SZ_X : 0);
    const uint8_t* Bp = Bb + (size_t)z * SZ_W;
    const float* bias = (z == 0) ? bias0 : (z == 1) ? bias1 : bias2;

    if (t == 0) {
        MB_INIT(mb0, 1);  MB_INIT(mb0 + 8, 1);
        MB_INIT(mb0 + 16, 8);  MB_INIT(mb0 + 24, 8);
    }
    __syncthreads();

    auto load_chunk = [&](int c, int s) {
        const uint32_t sb = smb + s * STAGE;
        const uint32_t mb = mb0 + s * 8;
        MB_EXPECT(mb, STAGE);
        BULK_G2S(sb,         Ah + (size_t)c * A_PLANE + (size_t)m0 * 128, 16384, mb);
        BULK_G2S(sb + STG_B, Bp + (size_t)c * W_PLANE + (size_t)n0 * 128, 16384, mb);
    };

    const int l15   = lane & 15;
    const int uA    = lane >> 4;
    const int q3    = lane >> 3;
    const int brl   = lane & 7;
    const int brow  = (q3 < 2) ? brl : (8 + brl);
    const int uB    = q3 & 1;

    float acc[2][8][4];
    #pragma unroll
    for (int i = 0; i < 2; i++)
        #pragma unroll
        for (int j = 0; j < 8; j++)
            #pragma unroll
            for (int r = 0; r < 4; r++) acc[i][j][r] = 0.f;

    if (t == 0) load_chunk(0, 0);
    int pf[2] = {0, 0}, pe[2] = {0, 0};

    for (int c = 0; c < NCH; ++c) {
        const int s = c & 1;
        if (c + 1 < NCH && t == 0) {
            if (c >= 1) { MB_WAIT(mb0 + 16 + (s ^ 1) * 8, pe[s ^ 1]); pe[s ^ 1] ^= 1; }
            load_chunk(c + 1, s ^ 1);
        }
        MB_WAIT(mb0 + s * 8, pf[s]);
        pf[s] ^= 1;

        const uint32_t sb = smb + s * STAGE;
        #pragma unroll
        for (int k16 = 0; k16 < 64; k16 += 16) {
            uint32_t ah[2][4];
            #pragma unroll
            for (int mt = 0; mt < 2; mt++) {
                const int row = wm * 32 + mt * 16 + l15;
                const int u   = ((k16 >> 3) + uA) ^ (row & 7);
                const uint32_t ao = (uint32_t)(row * 128 + (u << 4));
                ldsm_x4(ah[mt], sb + ao);
            }
            #pragma unroll
            for (int p = 0; p < 4; p++) {
                const int row = wn * 64 + p * 16 + brow;
                const int u   = ((k16 >> 3) + uB) ^ (row & 7);
                const uint32_t bo = (uint32_t)(row * 128 + (u << 4));
                uint32_t rh[4];
                ldsm_x4(rh, sb + STG_B + bo);
                #pragma unroll
                for (int h = 0; h < 2; h++) {
                    const int nt = 2 * p + h;
                    #pragma unroll
                    for (int mt = 0; mt < 2; mt++)
                        mma_f16(acc[mt][nt], ah[mt], rh + 2 * h);
                }
            }
        }
        if (lane == 0) MB_ARRIVE(mb0 + 16 + s * 8);
    }

    const int gid = lane >> 2;
    const int qid = lane & 3;
    #pragma unroll
    for (int mt = 0; mt < 2; mt++) {
        #pragma unroll
        for (int nt = 0; nt < 8; nt++) {
            const int col = n0 + wn * 64 + nt * 8 + qid * 2;
            const float b0 = bias[col], b1 = bias[col + 1];
            #pragma unroll
            for (int half = 0; half < 2; half++) {
                const int row = m0 + wm * 32 + mt * 16 + gid + half * 8;
                float v0 = acc[mt][nt][half * 2]     + b0;
                float v1 = acc[mt][nt][half * 2 + 1] + b1;
                if (LAYER == 1) { v0 = gelu_exact(v0); v1 = gelu_exact(v1); }
                const size_t o = (LAYER == 1)
                    ? (size_t)z * SZ_X + toff(row, col, A_PLANE)
                    : (size_t)z * SLOT + PAD_B + toff(row, col, A_PLANE);
                *(uint32_t*)(C + o) = pack_f16(v0, v1);
            }
        }
    }
}

// ---------------------------------------------------------------------------
// Banded attention + LN, 512 threads, all-1-term (Q, K, S, V single fp16).
// p1: k-split (group g does chunks 6g..6g+5), partial-S fp32 reduce.
// p2: d-split (group g owns cols 384g..384g+383), Y in regs, fused LN.
// ---------------------------------------------------------------------------
__global__ void __launch_bounds__(512, 1) attn_kernel(
    const uint8_t* __restrict__ Qh, const uint8_t* __restrict__ Kh,
    const uint8_t* __restrict__ Vh,
    const float* __restrict__ lnw, const float* __restrict__ lnb,
    float* __restrict__ out)
{
    extern __shared__ char smc[];
    __shared__ uint64_t s_mb[12];
    __shared__ float2 s_part[32][8];
    const uint32_t smb = s2u(smc);
    const uint32_t smA = smb + AT_A;
    const uint32_t mb = s2u(&s_mb[0]);

    const int t    = threadIdx.x;
    const int warp = t >> 5;
    const int lane = t & 31;
    const int g    = warp >> 3;
    const int wg   = warp & 7;
    const int wm   = wg >> 2;
    const int wn   = wg & 3;
    const int gid  = lane >> 2;
    const int qid  = lane & 3;
    const int tg   = t & 255;

    const int bx = blockIdx.x;
    const int b  = bx >> 7;
    const int i0 = (bx & 127) * TQ;
    const long base = (long)b * 4096;
    const long gq   = base + i0;
    const long gk   = base + i0 - 256;
    const int jb = i0 - 256;

    const int l15  = lane & 15;
    const int uA   = lane >> 4;
    const int q3   = lane >> 3;
    const int brl  = lane & 7;
    const int brow = (q3 < 2) ? brl : (8 + brl);
    const int uB   = q3 & 1;

    if (t == 0) {
        #pragma unroll
        for (int i = 0; i < 4; i++) { MB_INIT(mb + i * 8, 1); MB_INIT(mb + 32 + i * 8, 8); }
        MB_INIT(mb + 64, 1); MB_INIT(mb + 72, 1);
        MB_INIT(mb + 80, 16); MB_INIT(mb + 88, 16);
    }
    __syncthreads();

    // phase 1: partial S over 6 chunks per group
    auto p1_load = [&](int cl, int s) {
        const int cg = g * 6 + cl;
        const uint32_t sb = smA + (g * 2 + s) * P1_STG;
        const uint32_t m1 = mb + (g * 2 + s) * 8;
        MB_EXPECT(m1, 40960);
        BULK_G2S(sb,         Kh + ((long)cg * A_PLANE + gk * 128), 36864, m1);
        BULK_G2S(sb + AT_QH, Qh + ((long)cg * A_PLANE + gq * 128), 4096, m1);
    };

    float acc[9][4];
    #pragma unroll
    for (int n = 0; n < 9; n++)
        #pragma unroll
        for (int r = 0; r < 4; r++) acc[n][r] = 0.f;

    if (tg == 0) { p1_load(0, 0); p1_load(1, 1); }
    int pf1[2] = {0, 0}, pe1[2] = {0, 0};

    for (int cl = 0; cl < 6; ++cl) {
        const int s = cl & 1;
        MB_WAIT(mb + (g * 2 + s) * 8, pf1[s]);
        pf1[s] ^= 1;

        const uint32_t sb = smA + (g * 2 + s) * P1_STG;
        #pragma unroll
        for (int k16 = 0; k16 < 64; k16 += 16) {
            uint32_t ah[4];
            {
                const int row = wm * 16 + l15;
                const int u   = ((k16 >> 3) + uA) ^ (row & 7);
                ldsm_x4(ah, sb + AT_QH + (uint32_t)(row * 128 + (u << 4)));
            }
            uint32_t bh[9][2];
            #pragma unroll
            for (int p = 0; p < 4; p++) {
                const int row = wn * 72 + p * 16 + brow;
                const int u   = ((k16 >> 3) + uB) ^ (row & 7);
                uint32_t r4[4];
                ldsm_x4(r4, sb + (uint32_t)(row * 128 + (u << 4)));
                bh[2*p][0] = r4[0]; bh[2*p][1] = r4[1];
                bh[2*p+1][0] = r4[2]; bh[2*p+1][1] = r4[3];
            }
            {
                const int row = wn * 72 + 64 + brl;
                const int u   = ((k16 >> 3) + ((lane >> 3) & 1)) ^ (row & 7);
                ldsm_x2(bh[8], sb + (uint32_t)(row * 128 + (u << 4)));
            }
            #pragma unroll
            for (int nt = 0; nt < 9; nt++)
                mma_f16(acc[nt], ah, bh[nt]);
        }
        if (lane == 0) MB_ARRIVE(mb + 32 + (g * 2 + s) * 8);
        if (tg == 0 && cl + 2 < 6) {
            MB_WAIT(mb + 32 + (g * 2 + s) * 8, pe1[s]); pe1[s] ^= 1;
            p1_load(cl + 2, s);
        }
    }

    // reduce partial S (group1 -> scratch; group0 adds, masks, packs fp16)
    __syncthreads();
    float* scr = (float*)(smc + AT_A);
    if (g == 1) {
        #pragma unroll
        for (int nt = 0; nt < 9; nt++)
            #pragma unroll
            for (int r = 0; r < 4; r++)
                scr[tg * 36 + nt * 4 + r] = acc[nt][r];
    }
    __syncthreads();
    if (g == 0) {
        #pragma unroll
        for (int nt = 0; nt < 9; nt++) {
            const int jw0 = wn * 72 + nt * 8 + qid * 2;
            #pragma unroll
            for (int half = 0; half < 2; half++) {
                const int ti = wm * 16 + gid + half * 8;
                float v0 = acc[nt][half * 2]     + scr[tg * 36 + nt * 4 + half * 2];
                float v1 = acc[nt][half * 2 + 1] + scr[tg * 36 + nt * 4 + half * 2 + 1];
                const bool ok0 = (jb + jw0     >= 0) && (jw0     > ti) && (jw0     <= ti + 256);
                const bool ok1 = (jb + jw0 + 1 >= 0) && (jw0 + 1 > ti) && (jw0 + 1 <= ti + 256);
                v0 = ok0 ? v0 * INV_SCALE : 0.f;
                v1 = ok1 ? v1 * INV_SCALE : 0.f;
                const uint32_t so = (uint32_t)(ti * SSTR + jw0) * 2;
                *(uint32_t*)(smc + AT_SH + so) = pack_f16(v0, v1);
            }
        }
    }
    __syncthreads();

    // phase 2: Y = S @ V (d-split by group)
    auto p2_load = [&](int js, int s) {
        const long r0 = gk + (long)js * 32;
        const uint32_t sb = smA + s * P2_STG;
        const uint32_t m2 = mb + 64 + s * 8;
        MB_EXPECT(m2, 49152);
        #pragma unroll
        for (int cv = 0; cv < 12; cv++)
            BULK_G2S(sb + cv * 4096, Vh + ((long)cv * A_PLANE + r0 * 128), 4096, m2);
    };

    float acc2[12][4];
    #pragma unroll
    for (int n = 0; n < 12; n++)
        #pragma unroll
        for (int r = 0; r < 4; r++) acc2[n][r] = 0.f;

    if (t == 0) { p2_load(0, 0); p2_load(1, 1); }
    int pf2[2] = {0, 0}, pe2[2] = {0, 0};

    for (int js = 0; js < 9; ++js) {
        const int s = js & 1;
        MB_WAIT(mb + 64 + s * 8, pf2[s]);
        pf2[s] ^= 1;

        const uint32_t sb = smA + s * P2_STG;
        #pragma unroll
        for (int k16 = 0; k16 < 32; k16 += 16) {
            uint32_t ah[4];
            const uint32_t ao = (uint32_t)((wm * 16 + l15) * SSTR + js * 32 + k16 + uA * 8) * 2;
            ldsm_x4(ah, smb + AT_SH + ao);

            const int row = k16 + l15;
            #pragma unroll
            for (int cp = 0; cp < 6; cp++) {
                const int cg = g * 384 + wn * 96 + cp * 16;
                const int cv = cg >> 6;
                const int u0 = (cg & 63) >> 3;
                const int u  = (u0 + uA) ^ (row & 7);
                const uint32_t bo = (uint32_t)(cv * 4096 + row * 128 + (u << 4));
                uint32_t r4[4];
                ldsm_x4_t(r4, sb + bo);
                mma_f16(acc2[2*cp],   ah, r4);
                mma_f16(acc2[2*cp+1], ah, r4 + 2);
            }
        }
        if (lane == 0) MB_ARRIVE(mb + 80 + s * 8);
        if (t == 0 && js + 2 < 9) {
            MB_WAIT(mb + 80 + s * 8, pe2[s]); pe2[s] ^= 1;
            p2_load(js + 2, s);
        }
    }

    // LN from registers
    {
        float sum[2] = {0.f, 0.f}, ssq[2] = {0.f, 0.f};
        #pragma unroll
        for (int nt = 0; nt < 12; nt++) {
            #pragma unroll
            for (int half = 0; half < 2; half++) {
                const float a = acc2[nt][half * 2];
                const float c = acc2[nt][half * 2 + 1];
                sum[half] += a + c;
                ssq[half] += a * a + c * c;
            }
        }
        #pragma unroll
        for (int o = 1; o <= 2; o <<= 1) {
            #pragma unroll
            for (int half = 0; half < 2; half++) {
                sum[half] += __shfl_xor_sync(0xffffffffu, sum[half], o);
                ssq[half] += __shfl_xor_sync(0xffffffffu, ssq[half], o);
            }
        }
        if (qid == 0) {
            #pragma unroll
            for (int half = 0; half < 2; half++) {
                const int row = wm * 16 + gid + half * 8;
                s_part[row][g * 4 + wn] = make_float2(sum[half], ssq[half]);
            }
        }
        __syncthreads();

        #pragma unroll
        for (int half = 0; half < 2; half++) {
            const int row = wm * 16 + gid + half * 8;
            float S = 0.f, SS = 0.f;
            #pragma unroll
            for (int i = 0; i < 8; i++) {
                const float2 p = s_part[row][i];
                S += p.x; SS += p.y;
            }
            const float mu   = S * (1.f / 768.f);
            const float var  = SS * (1.f / 768.f) - mu * mu;
            const float rstd = rsqrtf(var + 1e-5f);
            float* orow = out + (gq + row) * DD;
            #pragma unroll
            for (int nt = 0; nt < 12; nt++) {
                const int col = g * 384 + wn * 96 + (nt >> 1) * 16 + (nt & 1) * 8 + qid * 2;
                const float v0 = acc2[nt][half * 2];
                const float v1 = acc2[nt][half * 2 + 1];
                const float2 w2 = *(const float2*)(lnw + col);
                const float2 b2 = *(const float2*)(lnb + col);
                float2 r;
                r.x = (v0 - mu) * rstd * w2.x + b2.x;
                r.y = (v1 - mu) * rstd * w2.y + b2.y;
                *(float2*)(orow + col) = r;
            }
        }
    }
}

// ---------------------------------------------------------------------------
extern "C" void kernel_launch(void* const* d_in, const int* in_sizes, int n_in,
                              void* d_out, int out_size)
{
    const float* x   = (const float*)d_in[0];
    const float* qw1 = (const float*)d_in[1];
    const float* qb1 = (const float*)d_in[2];
    const float* qw2 = (const float*)d_in[3];
    const float* qb2 = (const float*)d_in[4];
    const float* kw1 = (const float*)d_in[5];
    const float* kb1 = (const float*)d_in[6];
    const float* kw2 = (const float*)d_in[7];
    const float* kb2 = (const float*)d_in[8];
    const float* vw1 = (const float*)d_in[9];
    const float* vb1 = (const float*)d_in[10];
    const float* vw2 = (const float*)d_in[11];
    const float* vb2 = (const float*)d_in[12];
    const float* lnw = (const float*)d_in[13];
    const float* lnb = (const float*)d_in[14];
    float* out = (float*)d_out;

    uint8_t *Xh, *Hh, *W1, *W2, *QKVh;
    cudaGetSymbolAddress((void**)&Xh, g_Xh);
    cudaGetSymbolAddress((void**)&Hh, g_Hh);
    cudaGetSymbolAddress((void**)&W1, g_W1);
    cudaGetSymbolAddress((void**)&W2, g_W2);
    cudaGetSymbolAddress((void**)&QKVh, g_QKVh);

    cudaFuncSetAttribute(mma_gemm_kernel<1>,
                         cudaFuncAttributeMaxDynamicSharedMemorySize, GEMM_SMEM);
    cudaFuncSetAttribute(mma_gemm_kernel<2>,
                         cudaFuncAttributeMaxDynamicSharedMemorySize, GEMM_SMEM);
    cudaFuncSetAttribute(attn_kernel,
                         cudaFuncAttributeMaxDynamicSharedMemorySize, ATTN_SMEM);

    convert_x_kernel<<<(MT * DD) / (256 * 8), 256>>>(x, Xh);

    const dim3 gw(24, 24, 6);
    const dim3 bw(32, 8);
    convert_wt_kernel<<<gw, bw>>>(qw1, kw1, vw1, qw2, kw2, vw2, W1, W2);

    const dim3 gg(DD / 128, MT / 128, 3);
    mma_gemm_kernel<1><<<gg, 256, GEMM_SMEM>>>(Xh, W1, qb1, kb1, vb1, Hh);
    mma_gemm_kernel<2><<<gg, 256, GEMM_SMEM>>>(Hh, W2, qb2, kb2, vb2, QKVh);

    attn_kernel<<<MT / TQ, 512, ATTN_SMEM>>>(
        QKVh + PAD_B,
        QKVh + SLOT + PAD_B,
        QKVh + 2ull * SLOT + PAD_B,
        lnw, lnb, out);
}